// round 6
// baseline (speedup 1.0000x reference)
#include <cuda_runtime.h>
#include <stdint.h>

#define KEHALF   7.199822675975274f
#define CUTOFF   10.0f
#define L2E      1.4426950408889634f
#define ZMAX     94
#define LUT_REP  32
#define NTHREADS 1024
#define TILE     2048            // edges per tile; 2 edges per thread
#define BYTES_R  (TILE * 12)     // 24576
#define BYTES_I  (TILE * 4)      //  8192
#define BYTES_ALL (BYTES_R + 2 * BYTES_I)

// per-atom z-index bytes (Z-1), built by prep kernel
__device__ __align__(16) uint8_t g_ztab[131072];

__device__ __forceinline__ float softplus_f(float x) {
    return (x > 20.0f) ? x : log1pf(__expf(x));
}

__global__ void k_prep(const float* __restrict__ Z, int N,
                       float* __restrict__ y, int M) {
    int i = blockIdx.x * blockDim.x + threadIdx.x;
    if (i < M) y[i] = 0.0f;
    if (i < N && i < 131072) g_ztab[i] = (uint8_t)((int)(Z[i] + 0.5f) - 1);
}

__device__ __forceinline__ uint32_t smem_u32(const void* p) {
    return (uint32_t)__cvta_generic_to_shared(p);
}

__device__ __forceinline__ void mbar_init(uint32_t mbar, uint32_t count) {
    asm volatile("mbarrier.init.shared.b64 [%0], %1;" :: "r"(mbar), "r"(count) : "memory");
}
__device__ __forceinline__ void mbar_expect_tx(uint32_t mbar, uint32_t bytes) {
    asm volatile("mbarrier.arrive.expect_tx.shared.b64 _, [%0], %1;"
                 :: "r"(mbar), "r"(bytes) : "memory");
}
__device__ __forceinline__ void mbar_wait(uint32_t mbar, uint32_t parity) {
    uint32_t done;
    asm volatile(
        "{\n\t.reg .pred p;\n\t"
        "mbarrier.try_wait.parity.acquire.cta.shared::cta.b64 p, [%1], %2;\n\t"
        "selp.b32 %0, 1, 0, p;\n\t}"
        : "=r"(done) : "r"(mbar), "r"(parity) : "memory");
    while (!done) {
        asm volatile(
            "{\n\t.reg .pred p;\n\t"
            "mbarrier.try_wait.parity.acquire.cta.shared::cta.b64 p, [%1], %2, 0x989680;\n\t"
            "selp.b32 %0, 1, 0, p;\n\t}"
            : "=r"(done) : "r"(mbar), "r"(parity) : "memory");
    }
}
__device__ __forceinline__ void bulk_ld(uint32_t smem_dst, const void* gmem_src,
                                        uint32_t bytes, uint32_t mbar) {
    asm volatile(
        "cp.async.bulk.shared::cta.global.mbarrier::complete_tx::bytes "
        "[%0], [%1], %2, [%3];"
        :: "r"(smem_dst), "l"(gmem_src), "r"(bytes), "r"(mbar) : "memory");
}

// cf layout: [0..3]=b, [4..7]=c, [8]=thr
__device__ __forceinline__ void do_edge(
    float rx, float ry, float rz, int zi, int zj, float zsum,
    float thr, const float* __restrict__ cf,
    float* bins, const int* __restrict__ im, int iatom)
{
    float s  = fmaf(rx, rx, fmaf(ry, ry, rz * rz));
    float rs = rsqrtf(s);
    float d  = s * rs;
    float t  = zsum * d;
    if (t < thr && d < CUTOFF) {                     // ~1% of edges survive
        float f = cf[4] * exp2f(-cf[0] * t) + cf[5] * exp2f(-cf[1] * t)
                + cf[6] * exp2f(-cf[2] * t) + cf[7] * exp2f(-cf[3] * t);
        float u  = d * (1.0f / CUTOFF);
        float u3 = u * u * u;
        float q  = fmaf(-6.0f, u, 15.0f);
        q        = fmaf(q, u, -10.0f);
        float fc = fmaf(u3, q, 1.0f);
        float Zi = (float)(zi + 1), Zj = (float)(zj + 1);
        float ee = KEHALF * f * fc * Zi * Zj * rs;
        if (ee != 0.0f) atomicAdd(&bins[im[iatom]], ee);
    }
}

__global__ __launch_bounds__(NTHREADS, 1) void k_edge(
    const float* __restrict__ r,
    const int*   __restrict__ ii,
    const int*   __restrict__ jj,
    const int*   __restrict__ im,
    const float* __restrict__ adiv,
    const float* __restrict__ apow,
    const float* __restrict__ av,
    const float* __restrict__ cv,
    int N, int E, float* __restrict__ y, int M)
{
    extern __shared__ __align__(128) char smem_raw[];
    // layout: tiles (2 stages) | bins | cf | zlut | mbar | ztab
    float*   tr0  = (float*)smem_raw;                       // 24KB
    int*     ti0  = (int*)(smem_raw + BYTES_R);             //  8KB
    int*     tj0  = (int*)(smem_raw + BYTES_R + BYTES_I);   //  8KB
    char*    st1  = smem_raw + BYTES_ALL;
    float*   tr1  = (float*)st1;
    int*     ti1  = (int*)(st1 + BYTES_R);
    int*     tj1  = (int*)(st1 + BYTES_R + BYTES_I);
    float*   bins = (float*)(smem_raw + 2 * BYTES_ALL);
    float*   cf   = bins + M;
    float*   zlut = cf + 16;
    uint64_t* mb  = (uint64_t*)(((uintptr_t)(zlut + ZMAX * LUT_REP) + 15) & ~(uintptr_t)15);
    uint8_t* ztab = (uint8_t*)(((uintptr_t)(mb + 2) + 15) & ~(uintptr_t)15);

    int tid  = threadIdx.x;
    int lane = tid & 31;
    int G    = gridDim.x;
    uint32_t mb0 = smem_u32(&mb[0]);
    uint32_t mb1 = smem_u32(&mb[1]);

    int NT = E / TILE;                      // full tiles
    int m  = 0;                             // tiles for this CTA
    for (int t = blockIdx.x; t < NT; t += G) m++;

    // ---- init + prologue TMA issue (tid 0) ----
    if (tid == 0) {
        mbar_init(mb0, 1);
        mbar_init(mb1, 1);
        // fence init before use by async proxy
        asm volatile("fence.proxy.async.shared::cta;" ::: "memory");
        if (m > 0) {
            long t0 = blockIdx.x;
            mbar_expect_tx(mb0, BYTES_ALL);
            bulk_ld(smem_u32(tr0), r  + t0 * TILE * 3, BYTES_R, mb0);
            bulk_ld(smem_u32(ti0), ii + t0 * TILE,     BYTES_I, mb0);
            bulk_ld(smem_u32(tj0), jj + t0 * TILE,     BYTES_I, mb0);
        }
        if (m > 1) {
            long t1 = blockIdx.x + G;
            mbar_expect_tx(mb1, BYTES_ALL);
            bulk_ld(smem_u32(tr1), r  + t1 * TILE * 3, BYTES_R, mb1);
            bulk_ld(smem_u32(ti1), ii + t1 * TILE,     BYTES_I, mb1);
            bulk_ld(smem_u32(tj1), jj + t1 * TILE,     BYTES_I, mb1);
        }
    }

    // ---- overlap: bins, coefficients, LUT, ztab staging ----
    for (int b = tid; b < M; b += blockDim.x) bins[b] = 0.0f;
    if (tid == 0) {
        float sp_adiv = softplus_f(adiv[0]);
        float a0 = softplus_f(av[0]), a1 = softplus_f(av[1]);
        float a2 = softplus_f(av[2]), a3 = softplus_f(av[3]);
        float c0 = softplus_f(cv[0]), c1 = softplus_f(cv[1]);
        float c2 = softplus_f(cv[2]), c3 = softplus_f(cv[3]);
        float cinv = 1.0f / (fabsf(c0) + fabsf(c1) + fabsf(c2) + fabsf(c3));
        float b0 = a0 * sp_adiv * L2E, b1 = a1 * sp_adiv * L2E;
        float b2 = a2 * sp_adiv * L2E, b3 = a3 * sp_adiv * L2E;
        cf[0] = b0; cf[1] = b1; cf[2] = b2; cf[3] = b3;
        cf[4] = c0 * cinv; cf[5] = c1 * cinv; cf[6] = c2 * cinv; cf[7] = c3 * cinv;
        float bmin = fminf(fminf(b0, b1), fminf(b2, b3));
        cf[8] = 151.0f / bmin;     // t >= thr -> all exp2 terms exactly 0.0f
    }
    {
        float spw = softplus_f(apow[0]);
        for (int k = tid; k < ZMAX * LUT_REP; k += blockDim.x) {
            int zi = k / LUT_REP;
            zlut[k] = exp2f(spw * log2f((float)(zi + 1)));
        }
    }
    {
        const int4* src = (const int4*)g_ztab;
        int4*       dst = (int4*)ztab;
        int n16 = N >> 4;
        for (int k = tid; k < n16; k += blockDim.x) dst[k] = src[k];
        for (int k = (n16 << 4) + tid; k < N; k += blockDim.x) ztab[k] = g_ztab[k];
    }
    __syncthreads();

    float thr = cf[8];

    // ---- main tile loop: double-buffered, CTA-synchronous ----
    float* trs[2] = {tr0, tr1};
    int*   tis[2] = {ti0, ti1};
    int*   tjs[2] = {tj0, tj1};
    uint32_t mbs[2] = {mb0, mb1};

    for (int k = 0; k < m; k++) {
        int s = k & 1;
        mbar_wait(mbs[s], (k >> 1) & 1);

        const float* rt = trs[s];
        const int*   it = tis[s];
        const int*   jt = tjs[s];

        // 2 contiguous edges per thread
        int   p  = 2 * tid;
        float x0 = rt[6 * tid + 0], y0 = rt[6 * tid + 1], z0 = rt[6 * tid + 2];
        float x1 = rt[6 * tid + 3], y1 = rt[6 * tid + 4], z1 = rt[6 * tid + 5];
        int   i0 = it[p], i1 = it[p + 1];
        int   j0 = jt[p], j1 = jt[p + 1];

        int zi0 = ztab[i0], zj0 = ztab[j0];
        int zi1 = ztab[i1], zj1 = ztab[j1];
        float zs0 = zlut[zi0 * LUT_REP + lane] + zlut[zj0 * LUT_REP + lane];
        float zs1 = zlut[zi1 * LUT_REP + lane] + zlut[zj1 * LUT_REP + lane];

        do_edge(x0, y0, z0, zi0, zj0, zs0, thr, cf, bins, im, i0);
        do_edge(x1, y1, z1, zi1, zj1, zs1, thr, cf, bins, im, i1);

        __syncthreads();   // everyone done reading stage s

        if (tid == 0 && (k + 2) < m) {
            long tn = blockIdx.x + (long)(k + 2) * G;
            mbar_expect_tx(mbs[s], BYTES_ALL);
            bulk_ld(smem_u32(trs[s]), r  + tn * TILE * 3, BYTES_R, mbs[s]);
            bulk_ld(smem_u32(tis[s]), ii + tn * TILE,     BYTES_I, mbs[s]);
            bulk_ld(smem_u32(tjs[s]), jj + tn * TILE,     BYTES_I, mbs[s]);
        }
    }

    // ---- tail edges (E % TILE) by block 0, straight from gmem ----
    if (blockIdx.x == 0) {
        for (int e = NT * TILE + tid; e < E; e += blockDim.x) {
            int i = ii[e], j = jj[e];
            int zi = ztab[i], zj = ztab[j];
            float zsum = zlut[zi * LUT_REP + lane] + zlut[zj * LUT_REP + lane];
            do_edge(r[3 * e], r[3 * e + 1], r[3 * e + 2],
                    zi, zj, zsum, thr, cf, bins, im, i);
        }
    }

    __syncthreads();
    for (int b = tid; b < M; b += blockDim.x) {
        float v = bins[b];
        if (v != 0.0f) atomicAdd(&y[b], v);
    }
}

extern "C" void kernel_launch(void* const* d_in, const int* in_sizes, int n_in,
                              void* d_out, int out_size) {
    const float* Z    = (const float*)d_in[0];
    const float* r    = (const float*)d_in[1];
    const int*   ii   = (const int*)  d_in[2];
    const int*   jj   = (const int*)  d_in[3];
    const int*   im   = (const int*)  d_in[4];
    const float* adiv = (const float*)d_in[5];
    const float* apow = (const float*)d_in[6];
    const float* av   = (const float*)d_in[7];
    const float* cv   = (const float*)d_in[8];

    int N = in_sizes[0];
    int E = in_sizes[2];
    int M = out_size;
    float* y = (float*)d_out;

    int prep_n = (N > M ? N : M);
    k_prep<<<(prep_n + 255) / 256, 256>>>(Z, N, y, M);

    int sm_count = 148;
    cudaDeviceGetAttribute(&sm_count, cudaDevAttrMultiProcessorCount, 0);

    size_t smem = 2 * BYTES_ALL                    // tile double buffer
                + (size_t)M * 4 + 16 * 4           // bins + cf
                + (size_t)ZMAX * LUT_REP * 4       // zlut
                + 64                               // mbarriers + align pad
                + (size_t)N + 32;                  // ztab
    cudaFuncSetAttribute(k_edge,
                         cudaFuncAttributeMaxDynamicSharedMemorySize, (int)smem);
    k_edge<<<sm_count, NTHREADS, smem>>>(
        r, ii, jj, im, adiv, apow, av, cv, N, E, y, M);
}

// round 7
// speedup vs baseline: 1.0779x; 1.0779x over previous
#include <cuda_runtime.h>
#include <stdint.h>

#define KEHALF   7.199822675975274f
#define CUTOFF   10.0f
#define L2E      1.4426950408889634f
#define ZMAX     94
#define LUT_REP  8
#define NTHREADS 1024

// per-atom z-index bytes (Z-1), built by prep kernel
__device__ __align__(16) uint8_t g_ztab[131072];

__device__ __forceinline__ float softplus_f(float x) {
    return (x > 20.0f) ? x : log1pf(__expf(x));
}

__global__ void k_prep(const float* __restrict__ Z, int N,
                       float* __restrict__ y, int M) {
    int i = blockIdx.x * blockDim.x + threadIdx.x;
    if (i < M) y[i] = 0.0f;
    if (i < N && i < 131072) g_ztab[i] = (uint8_t)((int)(Z[i] + 0.5f) - 1);
}

// cf layout: [0..3]=b, [4..7]=c, [8]=thr
__device__ __forceinline__ void do_edge(
    float rx, float ry, float rz, int zi, int zj, float zsum,
    float thr, const float* __restrict__ cf,
    float* bins, const int* __restrict__ im, int iatom)
{
    float s  = fmaf(rx, rx, fmaf(ry, ry, rz * rz));
    float rs = rsqrtf(s);
    float d  = s * rs;
    float t  = zsum * d;
    if (t < thr && d < CUTOFF) {                     // ~1% of edges survive
        float f = cf[4] * exp2f(-cf[0] * t) + cf[5] * exp2f(-cf[1] * t)
                + cf[6] * exp2f(-cf[2] * t) + cf[7] * exp2f(-cf[3] * t);
        float u  = d * (1.0f / CUTOFF);
        float u3 = u * u * u;
        float q  = fmaf(-6.0f, u, 15.0f);
        q        = fmaf(q, u, -10.0f);
        float fc = fmaf(u3, q, 1.0f);
        float Zi = (float)(zi + 1), Zj = (float)(zj + 1);
        float ee = KEHALF * f * fc * Zi * Zj * rs;
        if (ee != 0.0f) atomicAdd(&bins[im[iatom]], ee);
    }
}

__global__ __launch_bounds__(NTHREADS, 2) void k_edge(
    const float* __restrict__ r,
    const int*   __restrict__ ii,
    const int*   __restrict__ jj,
    const int*   __restrict__ im,
    const float* __restrict__ adiv,
    const float* __restrict__ apow,
    const float* __restrict__ av,
    const float* __restrict__ cv,
    int N, int E, float* __restrict__ y, int M)
{
    extern __shared__ __align__(16) char smem_raw[];
    float*   bins = (float*)smem_raw;                 // M floats (4KB)
    float*   cf   = bins + M;                         // 16 floats
    float*   zlut = cf + 16;                          // 94*8 floats (3KB)
    uint8_t* ztab = (uint8_t*)(((uintptr_t)(zlut + ZMAX * LUT_REP) + 15)
                               & ~(uintptr_t)15);     // N bytes (~100KB)

    int tid  = threadIdx.x;
    int lane = tid & (LUT_REP - 1);

    for (int b = tid; b < M; b += blockDim.x) bins[b] = 0.0f;

    if (tid == 0) {
        float sp_adiv = softplus_f(adiv[0]);
        float a0 = softplus_f(av[0]), a1 = softplus_f(av[1]);
        float a2 = softplus_f(av[2]), a3 = softplus_f(av[3]);
        float c0 = softplus_f(cv[0]), c1 = softplus_f(cv[1]);
        float c2 = softplus_f(cv[2]), c3 = softplus_f(cv[3]);
        float cinv = 1.0f / (fabsf(c0) + fabsf(c1) + fabsf(c2) + fabsf(c3));
        float b0 = a0 * sp_adiv * L2E, b1 = a1 * sp_adiv * L2E;
        float b2 = a2 * sp_adiv * L2E, b3 = a3 * sp_adiv * L2E;
        cf[0] = b0; cf[1] = b1; cf[2] = b2; cf[3] = b3;
        cf[4] = c0 * cinv; cf[5] = c1 * cinv; cf[6] = c2 * cinv; cf[7] = c3 * cinv;
        float bmin = fminf(fminf(b0, b1), fminf(b2, b3));
        cf[8] = 151.0f / bmin;     // t >= thr -> every exp2 term is exactly 0.0f
    }

    {   // bank-replicated z-LUT (8-way)
        float spw = softplus_f(apow[0]);
        for (int k = tid; k < ZMAX * LUT_REP; k += blockDim.x) {
            int zi = k / LUT_REP;
            zlut[k] = exp2f(spw * log2f((float)(zi + 1)));
        }
    }

    {   // stage byte table into smem
        const int4* src = (const int4*)g_ztab;
        int4*       dst = (int4*)ztab;
        int n16 = N >> 4;
        for (int k = tid; k < n16; k += blockDim.x) dst[k] = src[k];
        for (int k = (n16 << 4) + tid; k < N; k += blockDim.x) ztab[k] = g_ztab[k];
    }

    __syncthreads();

    float thr = cf[8];

    int E2     = E & ~1;
    int stride = gridDim.x * blockDim.x * 2;

    for (int e = (blockIdx.x * blockDim.x + tid) * 2; e < E2; e += stride) {
        // 2 consecutive edges: 3x LDG.64 (r) + 2x LDG.64 (indices)
        const float* rp = r + 3 * e;
        float2 p0 = __ldcs((const float2*)(rp + 0));
        float2 p1 = __ldcs((const float2*)(rp + 2));
        float2 p2 = __ldcs((const float2*)(rp + 4));
        int2   iv = __ldcs((const int2*)(ii + e));
        int2   jv = __ldcs((const int2*)(jj + e));

        int zi0 = ztab[iv.x], zj0 = ztab[jv.x];
        int zi1 = ztab[iv.y], zj1 = ztab[jv.y];

        float zs0 = zlut[zi0 * LUT_REP + lane] + zlut[zj0 * LUT_REP + lane];
        float zs1 = zlut[zi1 * LUT_REP + lane] + zlut[zj1 * LUT_REP + lane];

        do_edge(p0.x, p0.y, p1.x, zi0, zj0, zs0, thr, cf, bins, im, iv.x);
        do_edge(p1.y, p2.x, p2.y, zi1, zj1, zs1, thr, cf, bins, im, iv.y);
    }

    // odd tail edge
    if (blockIdx.x == 0 && tid == 0 && (E & 1)) {
        int e = E - 1;
        int i = ii[e], j = jj[e];
        int zi = ztab[i], zj = ztab[j];
        float zsum = zlut[zi * LUT_REP + lane] + zlut[zj * LUT_REP + lane];
        do_edge(r[3 * e], r[3 * e + 1], r[3 * e + 2],
                zi, zj, zsum, thr, cf, bins, im, i);
    }

    __syncthreads();
    for (int b = tid; b < M; b += blockDim.x) {
        float v = bins[b];
        if (v != 0.0f) atomicAdd(&y[b], v);
    }
}

extern "C" void kernel_launch(void* const* d_in, const int* in_sizes, int n_in,
                              void* d_out, int out_size) {
    const float* Z    = (const float*)d_in[0];
    const float* r    = (const float*)d_in[1];
    const int*   ii   = (const int*)  d_in[2];
    const int*   jj   = (const int*)  d_in[3];
    const int*   im   = (const int*)  d_in[4];
    const float* adiv = (const float*)d_in[5];
    const float* apow = (const float*)d_in[6];
    const float* av   = (const float*)d_in[7];
    const float* cv   = (const float*)d_in[8];

    int N = in_sizes[0];
    int E = in_sizes[2];
    int M = out_size;
    float* y = (float*)d_out;

    int prep_n = (N > M ? N : M);
    k_prep<<<(prep_n + 255) / 256, 256>>>(Z, N, y, M);

    int sm_count = 148;
    cudaDeviceGetAttribute(&sm_count, cudaDevAttrMultiProcessorCount, 0);

    size_t smem = (size_t)M * 4 + 16 * 4
                + (size_t)ZMAX * LUT_REP * 4
                + 32 + (size_t)N;              // ~107.2 KB -> 2 CTAs/SM
    cudaFuncSetAttribute(k_edge,
                         cudaFuncAttributeMaxDynamicSharedMemorySize, (int)smem);
    k_edge<<<2 * sm_count, NTHREADS, smem>>>(
        r, ii, jj, im, adiv, apow, av, cv, N, E, y, M);
}

// round 8
// speedup vs baseline: 1.4849x; 1.3776x over previous
#include <cuda_runtime.h>
#include <stdint.h>

#define KEHALF   7.199822675975274f
#define CUTOFF   10.0f
#define L2E      1.4426950408889634f
#define ZMAX     94
#define LUT_REP  32
#define CHUNK    4
#define NTHREADS 1024

// per-atom z-index bytes (Z-1), built by prep kernel
__device__ __align__(16) uint8_t g_ztab[131072];

__device__ __forceinline__ float softplus_f(float x) {
    return (x > 20.0f) ? x : log1pf(__expf(x));
}

__global__ void k_prep(const float* __restrict__ Z, int N,
                       float* __restrict__ y, int M) {
    int i = blockIdx.x * blockDim.x + threadIdx.x;
    if (i < M) y[i] = 0.0f;
    if (i < N && i < 131072) g_ztab[i] = (uint8_t)((int)(Z[i] + 0.5f) - 1);
}

struct Chunk {
    float4 p0, p1, p2;   // 12 floats = 4 edges x (rx,ry,rz)
    int4   iv, jv;
};

__device__ __forceinline__ Chunk load_chunk(const float4* __restrict__ rv,
                                            const int* __restrict__ ii,
                                            const int* __restrict__ jj,
                                            int e0) {
    Chunk c;
    int fi = (e0 >> 2) * 3;
    c.p0 = __ldcs(rv + fi + 0);
    c.p1 = __ldcs(rv + fi + 1);
    c.p2 = __ldcs(rv + fi + 2);
    c.iv = __ldcs((const int4*)(ii + e0));
    c.jv = __ldcs((const int4*)(jj + e0));
    return c;
}

// cf layout: [0..3]=b, [4..7]=c, [8]=thr2 (thr squared), [9]=thr
__device__ __forceinline__ void do_edge(
    float rx, float ry, float rz, int zi, int zj, float zsum,
    float thr2, const float* __restrict__ cf,
    float* bins, const int* __restrict__ im, int iatom)
{
    float s = fmaf(rx, rx, fmaf(ry, ry, rz * rz));   // d^2
    float q = (zsum * zsum) * s;                      // t^2

    // Squared-space survival test: t < thr && d < CUTOFF  (no sqrt needed).
    // Non-survivors contribute exactly 0 (all exp2 terms underflow to 0.0f).
    if (q < thr2 && s < CUTOFF * CUTOFF) {            // ~0.3% of edges
        float rs = rsqrtf(s);                         // MUFU only on survivors
        float d  = s * rs;
        float t  = zsum * d;
        float f = cf[4] * exp2f(-cf[0] * t) + cf[5] * exp2f(-cf[1] * t)
                + cf[6] * exp2f(-cf[2] * t) + cf[7] * exp2f(-cf[3] * t);
        float u  = d * (1.0f / CUTOFF);
        float u3 = u * u * u;
        float p  = fmaf(-6.0f, u, 15.0f);
        p        = fmaf(p, u, -10.0f);
        float fc = fmaf(u3, p, 1.0f);
        float Zi = (float)(zi + 1), Zj = (float)(zj + 1);
        float ee = KEHALF * f * fc * Zi * Zj * rs;
        if (ee != 0.0f) atomicAdd(&bins[im[iatom]], ee);
    }
}

__device__ __forceinline__ void process_chunk(
    const Chunk& c, const uint8_t* __restrict__ ztab,
    const float* __restrict__ zlut, float thr2, const float* __restrict__ cf,
    float* bins, const int* __restrict__ im, int lane)
{
    int ia[CHUNK] = {c.iv.x, c.iv.y, c.iv.z, c.iv.w};
    int ja[CHUNK] = {c.jv.x, c.jv.y, c.jv.z, c.jv.w};
    float fx[12]  = {c.p0.x, c.p0.y, c.p0.z, c.p0.w,
                     c.p1.x, c.p1.y, c.p1.z, c.p1.w,
                     c.p2.x, c.p2.y, c.p2.z, c.p2.w};

    int zi[CHUNK], zj[CHUNK];
    #pragma unroll
    for (int k = 0; k < CHUNK; k++) {
        zi[k] = ztab[ia[k]];
        zj[k] = ztab[ja[k]];
    }
    float zs[CHUNK];
    #pragma unroll
    for (int k = 0; k < CHUNK; k++)
        zs[k] = zlut[zi[k] * LUT_REP + lane] + zlut[zj[k] * LUT_REP + lane];

    #pragma unroll
    for (int k = 0; k < CHUNK; k++)
        do_edge(fx[3 * k], fx[3 * k + 1], fx[3 * k + 2],
                zi[k], zj[k], zs[k], thr2, cf, bins, im, ia[k]);
}

__global__ __launch_bounds__(NTHREADS, 1) void k_edge(
    const float* __restrict__ r,
    const int*   __restrict__ ii,
    const int*   __restrict__ jj,
    const int*   __restrict__ im,
    const float* __restrict__ adiv,
    const float* __restrict__ apow,
    const float* __restrict__ av,
    const float* __restrict__ cv,
    int N, int E, float* __restrict__ y, int M)
{
    extern __shared__ char smem_raw[];
    float*   bins = (float*)smem_raw;
    float*   cf   = bins + M;                 // 16 floats (coef block)
    float*   zlut = cf + 16;
    uint8_t* ztab = (uint8_t*)(((uintptr_t)(zlut + ZMAX * LUT_REP) + 15) & ~(uintptr_t)15);

    int tid  = threadIdx.x;
    int lane = tid & 31;

    for (int b = tid; b < M; b += blockDim.x) bins[b] = 0.0f;

    if (tid == 0) {
        float sp_adiv = softplus_f(adiv[0]);
        float a0 = softplus_f(av[0]), a1 = softplus_f(av[1]);
        float a2 = softplus_f(av[2]), a3 = softplus_f(av[3]);
        float c0 = softplus_f(cv[0]), c1 = softplus_f(cv[1]);
        float c2 = softplus_f(cv[2]), c3 = softplus_f(cv[3]);
        float cinv = 1.0f / (fabsf(c0) + fabsf(c1) + fabsf(c2) + fabsf(c3));
        float b0 = a0 * sp_adiv * L2E, b1 = a1 * sp_adiv * L2E;
        float b2 = a2 * sp_adiv * L2E, b3 = a3 * sp_adiv * L2E;
        cf[0] = b0; cf[1] = b1; cf[2] = b2; cf[3] = b3;
        cf[4] = c0 * cinv; cf[5] = c1 * cinv; cf[6] = c2 * cinv; cf[7] = c3 * cinv;
        float bmin = fminf(fminf(b0, b1), fminf(b2, b3));
        float thr  = 151.0f / bmin;  // t >= thr => every exp2 term is exactly 0.0f
        cf[8] = thr * thr;
        cf[9] = thr;
    }

    // bank-replicated z-LUT: zlut[zi*32 + lane] -> bank == lane, conflict-free
    {
        float spw = softplus_f(apow[0]);
        for (int k = tid; k < ZMAX * LUT_REP; k += blockDim.x) {
            int zi = k / LUT_REP;
            zlut[k] = exp2f(spw * log2f((float)(zi + 1)));
        }
    }

    {   // stage byte table into smem
        const int4* src = (const int4*)g_ztab;
        int4*       dst = (int4*)ztab;
        int n16 = N >> 4;
        for (int k = tid; k < n16; k += blockDim.x) dst[k] = src[k];
        for (int k = (n16 << 4) + tid; k < N; k += blockDim.x) ztab[k] = g_ztab[k];
    }

    __syncthreads();

    float thr2 = cf[8];

    int stride = gridDim.x * blockDim.x * CHUNK;
    int E4     = E & ~(CHUNK - 1);
    const float4* rv = (const float4*)r;

    int e = (blockIdx.x * blockDim.x + tid) * CHUNK;

    // ---- 2-deep software pipeline over chunk iterations ----
    if (e < E4) {
        Chunk cur = load_chunk(rv, ii, jj, e);
        while (true) {
            int  en   = e + stride;
            bool hasn = (en < E4);
            Chunk nxt;
            if (hasn) nxt = load_chunk(rv, ii, jj, en);   // in flight during compute
            process_chunk(cur, ztab, zlut, thr2, cf, bins, im, lane);
            if (!hasn) break;
            cur = nxt;
            e   = en;
        }
    }

    // scalar tail (E not multiple of CHUNK)
    if (blockIdx.x == 0) {
        for (int t = E4 + tid; t < E; t += blockDim.x) {
            int i = ii[t], j = jj[t];
            int zi = ztab[i], zj = ztab[j];
            float zsum = zlut[zi * LUT_REP + lane] + zlut[zj * LUT_REP + lane];
            do_edge(r[3 * t], r[3 * t + 1], r[3 * t + 2],
                    zi, zj, zsum, thr2, cf, bins, im, i);
        }
    }

    __syncthreads();
    for (int b = tid; b < M; b += blockDim.x) {
        float v = bins[b];
        if (v != 0.0f) atomicAdd(&y[b], v);
    }
}

extern "C" void kernel_launch(void* const* d_in, const int* in_sizes, int n_in,
                              void* d_out, int out_size) {
    const float* Z    = (const float*)d_in[0];
    const float* r    = (const float*)d_in[1];
    const int*   ii   = (const int*)  d_in[2];
    const int*   jj   = (const int*)  d_in[3];
    const int*   im   = (const int*)  d_in[4];
    const float* adiv = (const float*)d_in[5];
    const float* apow = (const float*)d_in[6];
    const float* av   = (const float*)d_in[7];
    const float* cv   = (const float*)d_in[8];

    int N = in_sizes[0];
    int E = in_sizes[2];
    int M = out_size;
    float* y = (float*)d_out;

    int prep_n = (N > M ? N : M);
    k_prep<<<(prep_n + 255) / 256, 256>>>(Z, N, y, M);

    int sm_count = 148;
    cudaDeviceGetAttribute(&sm_count, cudaDevAttrMultiProcessorCount, 0);

    size_t smem = (size_t)M * 4 + 16 * 4 + (size_t)ZMAX * LUT_REP * 4 + 32 + (size_t)N;
    cudaFuncSetAttribute(k_edge,
                         cudaFuncAttributeMaxDynamicSharedMemorySize, (int)smem);
    k_edge<<<sm_count, NTHREADS, smem>>>(
        r, ii, jj, im, adiv, apow, av, cv, N, E, y, M);
}